// round 4
// baseline (speedup 1.0000x reference)
#include <cuda_runtime.h>
#include <cuda_bf16.h>
#include <cstdint>

// Problem constants (fixed shapes)
#define BB   4
#define LQ   1024
#define LKV  4096
#define CC   256
#define HH   8
#define DD   32
#define ZZ   1024

#define LOG2E 1.4426950408889634f

// Scratch buffers (allocation-free rule: __device__ globals)
__device__ float g_Q[BB * LQ  * CC];
__device__ float g_K[BB * LKV * CC];
__device__ float g_V[BB * LKV * CC];
__device__ float g_X[BB * LQ  * CC];

// ---------------------------------------------------------------------------
// tf32 helpers
// ---------------------------------------------------------------------------
__device__ __forceinline__ uint32_t f2tf(float f) {
    uint32_t u;
    asm("cvt.rna.tf32.f32 %0, %1;" : "=r"(u) : "f"(f));
    return u;
}

// D = A(16x8) * B(8x8) + D, tf32 inputs, fp32 accumulate
__device__ __forceinline__ void mma_tf32(float c[4], const uint32_t a[4], const uint32_t b[2]) {
    asm volatile(
        "mma.sync.aligned.m16n8k8.row.col.f32.tf32.tf32.f32 "
        "{%0,%1,%2,%3}, {%4,%5,%6,%7}, {%8,%9}, {%0,%1,%2,%3};"
        : "+f"(c[0]), "+f"(c[1]), "+f"(c[2]), "+f"(c[3])
        : "r"(a[0]), "r"(a[1]), "r"(a[2]), "r"(a[3]), "r"(b[0]), "r"(b[1]));
}

// ---------------------------------------------------------------------------
// tf32 mma GEMM: Y[m][n] = sum_k Xeff[m][k] * W[n][k] (+ bias)
// MODE 0: plain + bias (output projection)
// MODE 1: Xeff = X + ape[m % rowsPerBatch]  (q + q_ape)
// Block 128x64, BK=32, 8 warps as 4(m) x 2(n); warp tile 32x32.
// ---------------------------------------------------------------------------
template<int MODE>
__global__ __launch_bounds__(256)
void gemm_mma(const float* __restrict__ X, const float* __restrict__ ape,
              const float* __restrict__ W, const float* __restrict__ bias,
              float* __restrict__ Y, int rowsPerBatch)
{
    __shared__ uint32_t sA[128][36];
    __shared__ uint32_t sB[64][36];

    const int tid  = threadIdx.x;
    const int lane = tid & 31;
    const int w    = tid >> 5;
    const int wm   = w & 3;            // 0..3 (m)
    const int wn   = w >> 2;           // 0..1 (n)
    const int g    = lane >> 2;        // groupID 0..7
    const int t    = lane & 3;         // threadID_in_group 0..3
    const int m0   = blockIdx.y * 128;
    const int n0   = blockIdx.x * 64;

    float C[2][4][4] = {};

    for (int k0 = 0; k0 < CC; k0 += 32) {
        // load A tile 128x32 (APE fused)
        #pragma unroll
        for (int j = 0; j < 4; j++) {
            const int idx = tid + j * 256;
            const int row = idx >> 3;
            const int c4  = (idx & 7) * 4;
            const long m  = m0 + row;
            float4 a = *reinterpret_cast<const float4*>(&X[m * CC + k0 + c4]);
            if (MODE == 1) {
                const int lq = (int)(m % rowsPerBatch);
                const float4 e = *reinterpret_cast<const float4*>(&ape[(long)lq * CC + k0 + c4]);
                a.x += e.x; a.y += e.y; a.z += e.z; a.w += e.w;
            }
            sA[row][c4 + 0] = f2tf(a.x); sA[row][c4 + 1] = f2tf(a.y);
            sA[row][c4 + 2] = f2tf(a.z); sA[row][c4 + 3] = f2tf(a.w);
        }
        // load B tile 64x32
        #pragma unroll
        for (int j = 0; j < 2; j++) {
            const int idx = tid + j * 256;
            const int row = idx >> 3;
            const int c4  = (idx & 7) * 4;
            const float4 bv = *reinterpret_cast<const float4*>(&W[(long)(n0 + row) * CC + k0 + c4]);
            sB[row][c4 + 0] = f2tf(bv.x); sB[row][c4 + 1] = f2tf(bv.y);
            sB[row][c4 + 2] = f2tf(bv.z); sB[row][c4 + 3] = f2tf(bv.w);
        }
        __syncthreads();

        #pragma unroll
        for (int ks = 0; ks < 4; ks++) {
            uint32_t a[2][4];
            #pragma unroll
            for (int mt = 0; mt < 2; mt++) {
                const int rm = 32 * wm + 16 * mt;
                a[mt][0] = sA[rm + g    ][8 * ks + t];
                a[mt][1] = sA[rm + g + 8][8 * ks + t];
                a[mt][2] = sA[rm + g    ][8 * ks + t + 4];
                a[mt][3] = sA[rm + g + 8][8 * ks + t + 4];
            }
            uint32_t b[4][2];
            #pragma unroll
            for (int nt = 0; nt < 4; nt++) {
                b[nt][0] = sB[32 * wn + 8 * nt + g][8 * ks + t];
                b[nt][1] = sB[32 * wn + 8 * nt + g][8 * ks + t + 4];
            }
            #pragma unroll
            for (int mt = 0; mt < 2; mt++)
                #pragma unroll
                for (int nt = 0; nt < 4; nt++)
                    mma_tf32(C[mt][nt], a[mt], b[nt]);
        }
        __syncthreads();
    }

    // epilogue
    #pragma unroll
    for (int mt = 0; mt < 2; mt++) {
        #pragma unroll
        for (int nt = 0; nt < 4; nt++) {
            const int r0 = m0 + 32 * wm + 16 * mt + g;
            const int cc = n0 + 32 * wn + 8 * nt + 2 * t;
            float2 u = make_float2(C[mt][nt][0], C[mt][nt][1]);
            float2 v = make_float2(C[mt][nt][2], C[mt][nt][3]);
            if (MODE == 0) {
                u.x += bias[cc]; u.y += bias[cc + 1];
                v.x += bias[cc]; v.y += bias[cc + 1];
            }
            *reinterpret_cast<float2*>(&Y[(long)r0 * CC + cc]) = u;
            *reinterpret_cast<float2*>(&Y[(long)(r0 + 8) * CC + cc]) = v;
        }
    }
}

// ---------------------------------------------------------------------------
// Fused K+V projection (tf32 mma): one pass over kvm = kv (+k_ape rows>=Z)
// ---------------------------------------------------------------------------
__global__ __launch_bounds__(256)
void gemm_kv_mma(const float* __restrict__ X, const float* __restrict__ ape,
                 const float* __restrict__ Wk, const float* __restrict__ Wv,
                 float* __restrict__ Yk, float* __restrict__ Yv)
{
    __shared__ uint32_t sA [128][36];
    __shared__ uint32_t sBk[64][36];
    __shared__ uint32_t sBv[64][36];

    const int tid  = threadIdx.x;
    const int lane = tid & 31;
    const int w    = tid >> 5;
    const int wm   = w & 3;
    const int wn   = w >> 2;
    const int g    = lane >> 2;
    const int t    = lane & 3;
    const int m0   = blockIdx.y * 128;
    const int n0   = blockIdx.x * 64;

    float Ck[2][4][4] = {};
    float Cv[2][4][4] = {};

    for (int k0 = 0; k0 < CC; k0 += 32) {
        #pragma unroll
        for (int j = 0; j < 4; j++) {
            const int idx = tid + j * 256;
            const int row = idx >> 3;
            const int c4  = (idx & 7) * 4;
            const long m  = m0 + row;
            float4 a = *reinterpret_cast<const float4*>(&X[m * CC + k0 + c4]);
            const int lkv = (int)(m % LKV);
            if (lkv >= ZZ) {
                const float4 e = *reinterpret_cast<const float4*>(&ape[(long)(lkv - ZZ) * CC + k0 + c4]);
                a.x += e.x; a.y += e.y; a.z += e.z; a.w += e.w;
            }
            sA[row][c4 + 0] = f2tf(a.x); sA[row][c4 + 1] = f2tf(a.y);
            sA[row][c4 + 2] = f2tf(a.z); sA[row][c4 + 3] = f2tf(a.w);
        }
        #pragma unroll
        for (int j = 0; j < 2; j++) {
            const int idx = tid + j * 256;
            const int row = idx >> 3;
            const int c4  = (idx & 7) * 4;
            const float4 bk = *reinterpret_cast<const float4*>(&Wk[(long)(n0 + row) * CC + k0 + c4]);
            sBk[row][c4 + 0] = f2tf(bk.x); sBk[row][c4 + 1] = f2tf(bk.y);
            sBk[row][c4 + 2] = f2tf(bk.z); sBk[row][c4 + 3] = f2tf(bk.w);
            const float4 bv = *reinterpret_cast<const float4*>(&Wv[(long)(n0 + row) * CC + k0 + c4]);
            sBv[row][c4 + 0] = f2tf(bv.x); sBv[row][c4 + 1] = f2tf(bv.y);
            sBv[row][c4 + 2] = f2tf(bv.z); sBv[row][c4 + 3] = f2tf(bv.w);
        }
        __syncthreads();

        #pragma unroll
        for (int ks = 0; ks < 4; ks++) {
            uint32_t a[2][4];
            #pragma unroll
            for (int mt = 0; mt < 2; mt++) {
                const int rm = 32 * wm + 16 * mt;
                a[mt][0] = sA[rm + g    ][8 * ks + t];
                a[mt][1] = sA[rm + g + 8][8 * ks + t];
                a[mt][2] = sA[rm + g    ][8 * ks + t + 4];
                a[mt][3] = sA[rm + g + 8][8 * ks + t + 4];
            }
            #pragma unroll
            for (int nt = 0; nt < 4; nt++) {
                uint32_t bk[2], bv[2];
                bk[0] = sBk[32 * wn + 8 * nt + g][8 * ks + t];
                bk[1] = sBk[32 * wn + 8 * nt + g][8 * ks + t + 4];
                bv[0] = sBv[32 * wn + 8 * nt + g][8 * ks + t];
                bv[1] = sBv[32 * wn + 8 * nt + g][8 * ks + t + 4];
                #pragma unroll
                for (int mt = 0; mt < 2; mt++) {
                    mma_tf32(Ck[mt][nt], a[mt], bk);
                    mma_tf32(Cv[mt][nt], a[mt], bv);
                }
            }
        }
        __syncthreads();
    }

    #pragma unroll
    for (int mt = 0; mt < 2; mt++) {
        #pragma unroll
        for (int nt = 0; nt < 4; nt++) {
            const int r0 = m0 + 32 * wm + 16 * mt + g;
            const int cc = n0 + 32 * wn + 8 * nt + 2 * t;
            *reinterpret_cast<float2*>(&Yk[(long)r0 * CC + cc])       = make_float2(Ck[mt][nt][0], Ck[mt][nt][1]);
            *reinterpret_cast<float2*>(&Yk[(long)(r0 + 8) * CC + cc]) = make_float2(Ck[mt][nt][2], Ck[mt][nt][3]);
            *reinterpret_cast<float2*>(&Yv[(long)r0 * CC + cc])       = make_float2(Cv[mt][nt][0], Cv[mt][nt][1]);
            *reinterpret_cast<float2*>(&Yv[(long)(r0 + 8) * CC + cc]) = make_float2(Cv[mt][nt][2], Cv[mt][nt][3]);
        }
    }
}

// ---------------------------------------------------------------------------
// Flash attention with tf32 mma, softmax in exp2 domain.
// Block: BQ=128 q-rows, 8 warps; warp = 16 q-rows x all 32 kv cols of a tile.
// BK=32 per kv tile; online softmax fully in registers; Q frags preloaded.
// Q pre-scaled by scale*log2e; pos fused via FMA with log2e; exp == exp2.
// ---------------------------------------------------------------------------
__global__ __launch_bounds__(256)
void attn_mma(const float* __restrict__ Q, const float* __restrict__ Kp,
              const float* __restrict__ Vp, const float* __restrict__ pos,
              float* __restrict__ Xo)
{
    __shared__ uint32_t sK[2][32][36];   // [buf][kv][d] pad 36
    __shared__ uint32_t sV[2][32][40];   // [buf][kv][d] pad 40

    const int tid  = threadIdx.x;
    const int lane = tid & 31;
    const int w    = tid >> 5;          // 0..7, q-row block
    const int g    = lane >> 2;         // 0..7
    const int t    = lane & 3;          // 0..3
    const int b    = blockIdx.z;
    const int h    = blockIdx.y;
    const int q0   = blockIdx.x * 128;

    // scale * log2(e): softmax computed in exp2 domain
    const float qscale = 0.17677669529663687f * LOG2E;

    // ---- preload Q fragments (scaled), held for whole kernel ----
    uint32_t qf[4][4];
    {
        const long r0 = (long)(b * LQ + q0 + 16 * w + g) * CC + h * DD;
        const long r1 = r0 + 8L * CC;
        #pragma unroll
        for (int ks = 0; ks < 4; ks++) {
            qf[ks][0] = f2tf(qscale * Q[r0 + 8 * ks + t]);
            qf[ks][1] = f2tf(qscale * Q[r1 + 8 * ks + t]);
            qf[ks][2] = f2tf(qscale * Q[r0 + 8 * ks + t + 4]);
            qf[ks][3] = f2tf(qscale * Q[r1 + 8 * ks + t + 4]);
        }
    }

    float o[4][4] = {};            // O accum: [d-tile][reg], rows g/g+8
    float m0_ = -1e30f, m1_ = -1e30f;
    float l0_ = 0.0f,  l1_ = 0.0f;

    // tile loader (global -> regs)
    const int kr  = tid >> 3;          // 0..31
    const int kc4 = (tid & 7) * 4;     // 0,4,..28
    float4 kreg, vreg;
    {
        const long gg = (long)(b * LKV + kr) * CC + h * DD + kc4;
        kreg = *reinterpret_cast<const float4*>(&Kp[gg]);
        vreg = *reinterpret_cast<const float4*>(&Vp[gg]);
    }
    // store tile 0
    sK[0][kr][kc4 + 0] = f2tf(kreg.x); sK[0][kr][kc4 + 1] = f2tf(kreg.y);
    sK[0][kr][kc4 + 2] = f2tf(kreg.z); sK[0][kr][kc4 + 3] = f2tf(kreg.w);
    sV[0][kr][kc4 + 0] = f2tf(vreg.x); sV[0][kr][kc4 + 1] = f2tf(vreg.y);
    sV[0][kr][kc4 + 2] = f2tf(vreg.z); sV[0][kr][kc4 + 3] = f2tf(vreg.w);

    const int NT = LKV / 32;   // 128 kv tiles

    for (int kt = 0; kt < NT; kt++) {
        const int cur = kt & 1;
        const int k0  = kt * 32;
        __syncthreads();

        // issue next-tile global loads early (latency overlap)
        if (kt + 1 < NT) {
            const long gg = (long)(b * LKV + (k0 + 32) + kr) * CC + h * DD + kc4;
            kreg = *reinterpret_cast<const float4*>(&Kp[gg]);
            vreg = *reinterpret_cast<const float4*>(&Vp[gg]);
        }

        // ---- S = Q K^T for this warp: 16 x 32 (already in log2 domain) ----
        float s[4][4] = {};
        #pragma unroll
        for (int nt = 0; nt < 4; nt++) {
            #pragma unroll
            for (int ks = 0; ks < 4; ks++) {
                uint32_t bk[2];
                bk[0] = sK[cur][8 * nt + g][8 * ks + t];
                bk[1] = sK[cur][8 * nt + g][8 * ks + t + 4];
                mma_tf32(s[nt], qf[ks], bk);
            }
        }

        // ---- positional bias (kv < Z only), folded by log2e ----
        if (k0 < ZZ) {
            const long pr0 = ((long)(h * LQ + q0 + 16 * w + g)) * ZZ + k0;
            const long pr1 = pr0 + 8L * ZZ;
            #pragma unroll
            for (int nt = 0; nt < 4; nt++) {
                const float2 p0 = *reinterpret_cast<const float2*>(&pos[pr0 + 8 * nt + 2 * t]);
                const float2 p1 = *reinterpret_cast<const float2*>(&pos[pr1 + 8 * nt + 2 * t]);
                s[nt][0] = fmaf(p0.x, LOG2E, s[nt][0]);
                s[nt][1] = fmaf(p0.y, LOG2E, s[nt][1]);
                s[nt][2] = fmaf(p1.x, LOG2E, s[nt][2]);
                s[nt][3] = fmaf(p1.y, LOG2E, s[nt][3]);
            }
        }

        // ---- online softmax (register, 4-lane shuffle reductions) ----
        float mx0 = -1e30f, mx1 = -1e30f;
        #pragma unroll
        for (int nt = 0; nt < 4; nt++) {
            mx0 = fmaxf(mx0, fmaxf(s[nt][0], s[nt][1]));
            mx1 = fmaxf(mx1, fmaxf(s[nt][2], s[nt][3]));
        }
        mx0 = fmaxf(mx0, __shfl_xor_sync(0xffffffffu, mx0, 1));
        mx0 = fmaxf(mx0, __shfl_xor_sync(0xffffffffu, mx0, 2));
        mx1 = fmaxf(mx1, __shfl_xor_sync(0xffffffffu, mx1, 1));
        mx1 = fmaxf(mx1, __shfl_xor_sync(0xffffffffu, mx1, 2));

        const float mn0 = fmaxf(m0_, mx0);
        const float mn1 = fmaxf(m1_, mx1);
        const float al0 = exp2f(m0_ - mn0);
        const float al1 = exp2f(m1_ - mn1);
        m0_ = mn0; m1_ = mn1;

        float r0s = 0.0f, r1s = 0.0f;
        #pragma unroll
        for (int nt = 0; nt < 4; nt++) {
            s[nt][0] = exp2f(s[nt][0] - mn0);
            s[nt][1] = exp2f(s[nt][1] - mn0);
            s[nt][2] = exp2f(s[nt][2] - mn1);
            s[nt][3] = exp2f(s[nt][3] - mn1);
            r0s += s[nt][0] + s[nt][1];
            r1s += s[nt][2] + s[nt][3];
        }
        r0s += __shfl_xor_sync(0xffffffffu, r0s, 1);
        r0s += __shfl_xor_sync(0xffffffffu, r0s, 2);
        r1s += __shfl_xor_sync(0xffffffffu, r1s, 1);
        r1s += __shfl_xor_sync(0xffffffffu, r1s, 2);
        l0_ = l0_ * al0 + r0s;
        l1_ = l1_ * al1 + r1s;

        // ---- rescale O ----
        #pragma unroll
        for (int dt = 0; dt < 4; dt++) {
            o[dt][0] *= al0; o[dt][1] *= al0;
            o[dt][2] *= al1; o[dt][3] *= al1;
        }

        // ---- O += P V : remap P C-frags -> A-frags via shuffles ----
        const int src0 = (lane & ~3) | (t >> 1);
        const int src1 = (lane & ~3) | ((t >> 1) + 2);
        #pragma unroll
        for (int ks = 0; ks < 4; ks++) {
            const uint32_t p0 = f2tf(s[ks][0]);
            const uint32_t p1 = f2tf(s[ks][1]);
            const uint32_t p2 = f2tf(s[ks][2]);
            const uint32_t p3 = f2tf(s[ks][3]);
            uint32_t pa[4];
            {
                const uint32_t v00 = __shfl_sync(0xffffffffu, p0, src0);
                const uint32_t v01 = __shfl_sync(0xffffffffu, p1, src0);
                pa[0] = (t & 1) ? v01 : v00;
                const uint32_t v10 = __shfl_sync(0xffffffffu, p2, src0);
                const uint32_t v11 = __shfl_sync(0xffffffffu, p3, src0);
                pa[1] = (t & 1) ? v11 : v10;
                const uint32_t v20 = __shfl_sync(0xffffffffu, p0, src1);
                const uint32_t v21 = __shfl_sync(0xffffffffu, p1, src1);
                pa[2] = (t & 1) ? v21 : v20;
                const uint32_t v30 = __shfl_sync(0xffffffffu, p2, src1);
                const uint32_t v31 = __shfl_sync(0xffffffffu, p3, src1);
                pa[3] = (t & 1) ? v31 : v30;
            }
            #pragma unroll
            for (int dt = 0; dt < 4; dt++) {
                uint32_t bv[2];
                bv[0] = sV[cur][8 * ks + t    ][8 * dt + g];
                bv[1] = sV[cur][8 * ks + t + 4][8 * dt + g];
                mma_tf32(o[dt], pa, bv);
            }
        }

        // ---- stage next tile into the other buffer ----
        if (kt + 1 < NT) {
            const int nxt = cur ^ 1;
            sK[nxt][kr][kc4 + 0] = f2tf(kreg.x); sK[nxt][kr][kc4 + 1] = f2tf(kreg.y);
            sK[nxt][kr][kc4 + 2] = f2tf(kreg.z); sK[nxt][kr][kc4 + 3] = f2tf(kreg.w);
            sV[nxt][kr][kc4 + 0] = f2tf(vreg.x); sV[nxt][kr][kc4 + 1] = f2tf(vreg.y);
            sV[nxt][kr][kc4 + 2] = f2tf(vreg.z); sV[nxt][kr][kc4 + 3] = f2tf(vreg.w);
        }
    }

    // ---- finalize ----
    const float inv0 = 1.0f / l0_;
    const float inv1 = 1.0f / l1_;
    const long orow = (long)(b * LQ + q0 + 16 * w + g) * CC + h * DD;
    #pragma unroll
    for (int dt = 0; dt < 4; dt++) {
        *reinterpret_cast<float2*>(&Xo[orow + 8 * dt + 2 * t]) =
            make_float2(o[dt][0] * inv0, o[dt][1] * inv0);
        *reinterpret_cast<float2*>(&Xo[orow + 8L * CC + 8 * dt + 2 * t]) =
            make_float2(o[dt][2] * inv1, o[dt][3] * inv1);
    }
}

// ---------------------------------------------------------------------------
// Launch
// ---------------------------------------------------------------------------
extern "C" void kernel_launch(void* const* d_in, const int* in_sizes, int n_in,
                              void* d_out, int out_size)
{
    const float* q        = (const float*)d_in[0];
    const float* kv       = (const float*)d_in[1];
    const float* q_ape    = (const float*)d_in[2];
    const float* k_ape    = (const float*)d_in[3];
    const float* attn_pos = (const float*)d_in[4];
    const float* Wq       = (const float*)d_in[5];
    const float* Wk       = (const float*)d_in[6];
    const float* Wv       = (const float*)d_in[7];
    const float* Wp       = (const float*)d_in[8];
    const float* bp       = (const float*)d_in[9];
    float* out = (float*)d_out;

    float *Qp, *Kp, *Vp, *Xo;
    cudaGetSymbolAddress((void**)&Qp, g_Q);
    cudaGetSymbolAddress((void**)&Kp, g_K);
    cudaGetSymbolAddress((void**)&Vp, g_V);
    cudaGetSymbolAddress((void**)&Xo, g_X);

    // Projections (APE fused); K and V fused into one pass over kv
    gemm_mma<1><<<dim3(CC / 64, (BB * LQ) / 128), 256>>>(q, q_ape, Wq, nullptr, Qp, LQ);
    gemm_kv_mma<<<dim3(CC / 64, (BB * LKV) / 128), 256>>>(kv, k_ape, Wk, Wv, Kp, Vp);

    // Flash attention (tf32 mma, exp2-domain softmax)
    attn_mma<<<dim3(LQ / 128, HH, BB), 256>>>(Qp, Kp, Vp, attn_pos, Xo);

    // Output projection + bias
    gemm_mma<0><<<dim3(CC / 64, (BB * LQ) / 128), 256>>>(Xo, nullptr, Wp, bp, out, LQ);
}